// round 5
// baseline (speedup 1.0000x reference)
#include <cuda_runtime.h>
#include <cstdint>

// Haar inverse DWT2 (db1), fp32.  Inputs A,H,V,D: [8,32,256,256]; out: [8,32,512,512].
// x[2i,2j]=(A+H+V+D)/2; x[2i,2j+1]=(A+H-V-D)/2; x[2i+1,2j]=(A-H+V-D)/2; x[2i+1,2j+1]=(A-H-V+D)/2
//
// R5: R4 dataflow (one thread per float2, two STG.128, 18 regs) with block=1024:
// 32KB contiguous output + 8KB contiguous reads per input stream per CTA,
// maximizing same-page DRAM burst length per scheduling unit. 2 CTAs/SM still
// saturates the 2048-thread limit, so occupancy is structurally unchanged.

__global__ void __launch_bounds__(1024) idwt2_haar_kernel(
    const float2* __restrict__ A,
    const float2* __restrict__ H,
    const float2* __restrict__ V,
    const float2* __restrict__ D,
    float4* __restrict__ out)
{
    // total threads = 8*32*256*256 / 2 = 8,388,608
    const unsigned t = blockIdx.x * 1024u + threadIdx.x;

    const float2 a = __ldg(&A[t]);
    const float2 h = __ldg(&H[t]);
    const float2 v = __ldg(&V[t]);
    const float2 d = __ldg(&D[t]);

    float lp0 = a.x + h.x, lm0 = a.x - h.x;
    float mp0 = v.x + d.x, mm0 = v.x - d.x;
    float lp1 = a.y + h.y, lm1 = a.y - h.y;
    float mp1 = v.y + d.y, mm1 = v.y - d.y;

    float4 even, odd;
    even.x = (lp0 + mp0) * 0.5f;
    even.y = (lp0 - mp0) * 0.5f;
    even.z = (lp1 + mp1) * 0.5f;
    even.w = (lp1 - mp1) * 0.5f;
    odd.x  = (lm0 + mm0) * 0.5f;
    odd.y  = (lm0 - mm0) * 0.5f;
    odd.z  = (lm1 + mm1) * 0.5f;
    odd.w  = (lm1 - mm1) * 0.5f;

    // t = b*32768 + i*128 + j2 ; even-row out f4 index = ((t>>7)<<8) + (t&127)
    const unsigned o = ((t >> 7) << 8) + (t & 127u);
    out[o]        = even;
    out[o + 128u] = odd;   // odd row: +512 floats = +128 float4s
}

extern "C" void kernel_launch(void* const* d_in, const int* in_sizes, int n_in,
                              void* d_out, int out_size)
{
    const float2* A = (const float2*)d_in[0];
    const float2* H = (const float2*)d_in[1];
    const float2* V = (const float2*)d_in[2];
    const float2* D = (const float2*)d_in[3];
    float4* out = (float4*)d_out;

    const unsigned n_threads = (unsigned)(in_sizes[0] / 2);
    const unsigned blocks = (n_threads + 1023u) / 1024u;

    idwt2_haar_kernel<<<blocks, 1024>>>(A, H, V, D, out);
}